// round 3
// baseline (speedup 1.0000x reference)
#include <cuda_runtime.h>
#include <math.h>

// ---------------- scratch (static device allocations) ----------------
__device__ float g_band[8 * 1024 * 65];   // banded ATA -> L, [b][col][d], fp32
__device__ float g_atb[8 * 1024];         // rhs
__device__ float g_t[2 * 2 * 64 * 1024];  // conv1 outputs [branch][n][c][px]
__device__ float g_att[2 * 24 * 1024];    // sigmoid(conv2 att)
__device__ float g_grad[2 * 24 * 1024];   // conv2 grad
__device__ float g_se[2 * 4];
__device__ float g_sol[8 * 1024];
__device__ float g_ygn[2 * 4 * 1024];

// ---------------- conv1: 64->64 3x3, lrelu, both branches ----------------
__global__ void __launch_bounds__(256) k_conv1(
    const float* __restrict__ x,
    const float* __restrict__ gw1, const float* __restrict__ gb1,
    const float* __restrict__ aw1, const float* __restrict__ ab1)
{
    int plane  = blockIdx.x;           // 0..255
    int branch = plane >> 7;           // 0=grad, 1=att
    int n      = (plane >> 6) & 1;
    int co     = plane & 63;
    const float* wgt  = (branch ? aw1 : gw1) + co * 576;
    float bias        = (branch ? ab1 : gb1)[co];

    __shared__ float xs[34 * 34];
    int row  = threadIdx.x >> 3;        // 0..31
    int col0 = (threadIdx.x & 7) << 2;  // 0..28 step 4

    float a0 = bias, a1 = bias, a2 = bias, a3 = bias;
    const float* xbase = x + n * 64 * 1024;

    for (int ci = 0; ci < 64; ci++) {
        __syncthreads();
        const float* xp = xbase + ci * 1024;
        for (int idx = threadIdx.x; idx < 1156; idx += 256) {
            int r = idx / 34, c = idx - r * 34;
            int gr = r - 1, gc = c - 1;
            xs[idx] = ((unsigned)gr < 32u && (unsigned)gc < 32u) ? xp[gr * 32 + gc] : 0.f;
        }
        __syncthreads();
        float w[9];
#pragma unroll
        for (int k = 0; k < 9; k++) w[k] = __ldg(wgt + ci * 9 + k);
        float s[3][6];
#pragma unroll
        for (int dy = 0; dy < 3; dy++)
#pragma unroll
            for (int dx = 0; dx < 6; dx++)
                s[dy][dx] = xs[(row + dy) * 34 + col0 + dx];
#pragma unroll
        for (int dy = 0; dy < 3; dy++) {
            float w0 = w[dy * 3], w1 = w[dy * 3 + 1], w2 = w[dy * 3 + 2];
            a0 += w0 * s[dy][0] + w1 * s[dy][1] + w2 * s[dy][2];
            a1 += w0 * s[dy][1] + w1 * s[dy][2] + w2 * s[dy][3];
            a2 += w0 * s[dy][2] + w1 * s[dy][3] + w2 * s[dy][4];
            a3 += w0 * s[dy][3] + w1 * s[dy][4] + w2 * s[dy][5];
        }
    }
    float* out = g_t + (((branch * 2 + n) * 64 + co) * 1024) + row * 32 + col0;
    out[0] = a0 > 0.f ? a0 : 0.01f * a0;
    out[1] = a1 > 0.f ? a1 : 0.01f * a1;
    out[2] = a2 > 0.f ? a2 : 0.01f * a2;
    out[3] = a3 > 0.f ? a3 : 0.01f * a3;
}

// ---------------- conv2: 64->24 3x3 (+sigmoid on att branch) ----------------
__global__ void __launch_bounds__(256) k_conv2(
    const float* __restrict__ gw2, const float* __restrict__ gb2,
    const float* __restrict__ aw2, const float* __restrict__ ab2)
{
    int plane  = blockIdx.x;            // 0..95
    int branch = plane / 48;
    int rem    = plane - branch * 48;
    int n      = rem / 24;
    int co     = rem - n * 24;
    const float* wgt = (branch ? aw2 : gw2) + co * 576;
    float bias       = (branch ? ab2 : gb2)[co];

    __shared__ float xs[34 * 34];
    int row  = threadIdx.x >> 3;
    int col0 = (threadIdx.x & 7) << 2;

    float a0 = bias, a1 = bias, a2 = bias, a3 = bias;
    const float* xbase = g_t + (branch * 2 + n) * 64 * 1024;

    for (int ci = 0; ci < 64; ci++) {
        __syncthreads();
        const float* xp = xbase + ci * 1024;
        for (int idx = threadIdx.x; idx < 1156; idx += 256) {
            int r = idx / 34, c = idx - r * 34;
            int gr = r - 1, gc = c - 1;
            xs[idx] = ((unsigned)gr < 32u && (unsigned)gc < 32u) ? xp[gr * 32 + gc] : 0.f;
        }
        __syncthreads();
        float w[9];
#pragma unroll
        for (int k = 0; k < 9; k++) w[k] = __ldg(wgt + ci * 9 + k);
        float s[3][6];
#pragma unroll
        for (int dy = 0; dy < 3; dy++)
#pragma unroll
            for (int dx = 0; dx < 6; dx++)
                s[dy][dx] = xs[(row + dy) * 34 + col0 + dx];
#pragma unroll
        for (int dy = 0; dy < 3; dy++) {
            float w0 = w[dy * 3], w1 = w[dy * 3 + 1], w2 = w[dy * 3 + 2];
            a0 += w0 * s[dy][0] + w1 * s[dy][1] + w2 * s[dy][2];
            a1 += w0 * s[dy][1] + w1 * s[dy][2] + w2 * s[dy][3];
            a2 += w0 * s[dy][2] + w1 * s[dy][3] + w2 * s[dy][4];
            a3 += w0 * s[dy][3] + w1 * s[dy][4] + w2 * s[dy][5];
        }
    }
    float* out = (branch ? g_att : g_grad) + ((n * 24 + co) * 1024) + row * 32 + col0;
    if (branch) {
        out[0] = 1.f / (1.f + expf(-a0));
        out[1] = 1.f / (1.f + expf(-a1));
        out[2] = 1.f / (1.f + expf(-a2));
        out[3] = 1.f / (1.f + expf(-a3));
    } else {
        out[0] = a0; out[1] = a1; out[2] = a2; out[3] = a3;
    }
}

// ---------------- SE branch ----------------
__global__ void __launch_bounds__(256) k_se(
    const float* __restrict__ x,
    const float* __restrict__ sw1, const float* __restrict__ sb1,
    const float* __restrict__ sw2, const float* __restrict__ sb2)
{
    int n = blockIdx.x, tid = threadIdx.x;
    __shared__ float red[256];
    __shared__ float pooled[64];
    __shared__ float s1[32];

    int c = tid >> 2, part = tid & 3;
    const float* xp = x + (n * 64 + c) * 1024 + part * 256;
    float s = 0.f;
    for (int i = 0; i < 256; i++) s += xp[i];
    red[tid] = s;
    __syncthreads();
    if (part == 0)
        pooled[c] = (red[tid] + red[tid + 1] + red[tid + 2] + red[tid + 3]) * (1.f / 1024.f);
    __syncthreads();
    if (tid < 32) {
        float a = sb1[tid];
        for (int j = 0; j < 64; j++) a += sw1[tid * 64 + j] * pooled[j];
        s1[tid] = a > 0.f ? a : 0.01f * a;
    }
    __syncthreads();
    if (tid < 4) {
        float a = sb2[tid];
        for (int j = 0; j < 32; j++) a += sw2[tid * 32 + j] * s1[j];
        g_se[n * 4 + tid] = 1.f / (1.f + expf(-a));
    }
}

// ---------------- build banded ATA + ATB: deterministic gather ----------------
// Row (i,k) of `a` has support only at columns i + {0,1,2,31,32,33,64}.
// For output column q, diagonal d: contributions from offset pairs (c2,c1)
// with offs[c1]-offs[c2]==d, i=q-offs[c2]. Fully unrolled -> static accs.
__global__ void __launch_bounds__(256) k_build(const float* __restrict__ a)
{
    int t = blockIdx.x * blockDim.x + threadIdx.x;   // 0..8191
    int b = t >> 10;
    int q = t & 1023;
    int n = b >> 2;
    int g = b & 3;
    const int offs[7] = {0, 1, 2, 31, 32, 33, 64};

    float acc[11];  // d in DVALS below, unrolled statically
    const int DVALS[11] = {0, 1, 2, 29, 30, 31, 32, 33, 62, 63, 64};
#pragma unroll
    for (int z = 0; z < 11; z++) acc[z] = 0.f;
    acc[0] = 1e-12f;
    float atb = 0.f;

#pragma unroll
    for (int k = 0; k < 6; k++) {
        int ch = g * 6 + k;
        const float* attp  = g_att  + (n * 24 + ch) * 1024;
        const float* gradp = g_grad + (n * 24 + ch) * 1024;
#pragma unroll
        for (int c2 = 0; c2 < 7; c2++) {
            int i = q - offs[c2];
            if (i >= 0) {
                float attv = attp[i];
                float at2  = attv * attv;
                const float* arow = a + (size_t)(i * 6 + k) * 1024;
                float v2 = arow[q];
                if (v2 != 0.f) {
                    atb += v2 * at2 * gradp[i];
                    float w2 = v2 * at2;
#pragma unroll
                    for (int c1 = c2; c1 < 7; c1++) {
                        int col1 = i + offs[c1];
                        if (col1 <= 1023) {
                            float contrib = arow[col1] * w2;
                            int d = offs[c1] - offs[c2];
#pragma unroll
                            for (int z = 0; z < 11; z++)
                                if (DVALS[z] == d) acc[z] += contrib;
                        }
                    }
                }
            }
        }
    }

    float* bc = g_band + ((size_t)b * 1024 + q) * 65;
#pragma unroll
    for (int d = 0; d < 65; d++) {
        float v = 0.f;
#pragma unroll
        for (int z = 0; z < 11; z++)
            if (DVALS[z] == d) v = acc[z];
        bc[d] = v;
    }
    g_atb[b * 1024 + q] = atb;
}

// ---------------- register-resident banded Cholesky (fp32) ----------------
// One CTA per system. 256 threads = 32 (column classes) x 8 (diag groups).
// Thread (tc,td) owns band entries (col c, diag d) with c%32==tc, d in
// {td, td+8, ..., td+56} (+ d=64 for td==0), held in regs W[3][9].
// Per column step: pivot column was published to smem last step; everyone
// does a rank-1 update on its register tile; owners of the next pivot
// publish it. One __syncthreads per step.
__global__ void __launch_bounds__(256) k_solve()
{
    const int PF = 4;  // prefetch distance (steps)
    int b   = blockIdx.x;
    int tid = threadIdx.x;
    int tc  = tid & 31;
    int td  = tid >> 5;
    float* band = g_band + (size_t)b * 1024 * 65;

    __shared__ float Lsm[2][65];
    __shared__ float y_s[1024];
    __shared__ float x_s[1024];
    __shared__ float LB[64 * 65];   // back-sub block

    float W[3][9];
    float P[9];
    int   cidx[3];

    // ---- init: window columns 0..63 into slots 0,1; col 64..67 pending ----
    cidx[0] = tc;
    cidx[1] = tc + 32;
    cidx[2] = 0x40000000;
#pragma unroll
    for (int s = 0; s < 2; s++) {
        int c = cidx[s];
#pragma unroll
        for (int k = 0; k < 9; k++) {
            if (k == 8 && td != 0) break;
            int d = (k < 8) ? (td + 8 * k) : 64;
            W[s][k] = band[c * 65 + d];
        }
    }
    if (tc < PF) {
        int c = 64 + tc;
#pragma unroll
        for (int k = 0; k < 9; k++) {
            if (k == 8 && td != 0) break;
            int d = (k < 8) ? (td + 8 * k) : 64;
            P[k] = band[c * 65 + d];
        }
    }
    if (tc == 0) {   // publish column 0
#pragma unroll
        for (int k = 0; k < 9; k++) {
            if (k == 8 && td != 0) break;
            int d = (k < 8) ? (td + 8 * k) : 64;
            Lsm[0][d] = W[0][k];
        }
    }
    for (int j = tid; j < 1024; j += 256) y_s[j] = g_atb[b * 1024 + j];
    __syncthreads();

    // ---- factorization + fused forward substitution ----
    for (int j = 0; j < 1024; j++) {
        int buf = j & 1;
        const float* Lb = Lsm[buf];
        float d0  = Lb[0];
        float r0  = rsqrtf(d0);
        float inv = r0 * (1.5f - 0.5f * d0 * r0 * r0);  // 1 Newton step
        float inv2 = inv * inv;

        // commit pending column j+64
        if (tc == (j & 31) && j + 64 <= 1023) {
            int c = j + 64;
            int s = (c >> 5) % 3;
            cidx[s] = c;
#pragma unroll
            for (int k = 0; k < 9; k++) {
                if (k == 8 && td != 0) break;
                W[s][k] = P[k];
            }
        }

#pragma unroll
        for (int s = 0; s < 3; s++) {
            int o = cidx[s] - j;
            if (o == 0) {
                // pivot owner: write L column to gmem, forward-sub rhs
                float yjv = y_s[j];
                float* bcol = band + j * 65;
#pragma unroll
                for (int k = 0; k < 9; k++) {
                    if (k == 8 && td != 0) break;
                    int d = (k < 8) ? (td + 8 * k) : 64;
                    if (d == 0) {
                        bcol[0] = inv;            // store INVERSE diag
                        x_s[j]  = yjv * inv;      // forward-sub result
                    } else if (j + d <= 1023) {
                        bcol[d] = W[s][k] * inv;
                        y_s[j + d] -= W[s][k] * yjv * inv2;
                    }
                }
            } else if (o >= 1 && o <= 64) {
                float f = Lb[o] * inv2;
#pragma unroll
                for (int k = 0; k < 8; k++) {
                    int d = td + 8 * k;
                    if (o + d <= 64)
                        W[s][k] -= Lb[o + d] * f;
                }
                if (o == 1) {   // publish next pivot column (now final)
#pragma unroll
                    for (int k = 0; k < 9; k++) {
                        if (k == 8 && td != 0) break;
                        int d = (k < 8) ? (td + 8 * k) : 64;
                        Lsm[buf ^ 1][d] = W[s][k];
                    }
                }
            }
        }

        // prefetch column j+64+PF
        if (tc == ((j + PF) & 31)) {
            int c = j + 64 + PF;
            if (c <= 1023) {
#pragma unroll
                for (int k = 0; k < 9; k++) {
                    if (k == 8 && td != 0) break;
                    int d = (k < 8) ? (td + 8 * k) : 64;
                    P[k] = band[c * 65 + d];
                }
            }
        }
        __syncthreads();
    }

    // ---- back substitution: L^T x = y', blocked by 64 rows ----
    for (int blk = 15; blk >= 0; blk--) {
        int j0 = blk * 64;
        for (int idx = tid; idx < 64 * 65; idx += 256)
            LB[idx] = band[j0 * 65 + idx];
        __syncthreads();
        // tail contributions from finalized x in later blocks
        if (tid < 64) {
            int t = tid, jj = j0 + t;
            float s = 0.f;
            for (int r = 64 - t; r <= 64; r++) {
                int jr = jj + r;
                if (jr < 1024) s += LB[t * 65 + r] * x_s[jr];
            }
            x_s[jj] -= s;
        }
        __syncthreads();
        // in-block serial sweep (x kept unscaled; scale at the end)
        for (int t = 63; t >= 1; t--) {
            float xval = x_s[j0 + t] * LB[t * 65];
            if (tid < t) x_s[j0 + tid] -= LB[tid * 65 + (t - tid)] * xval;
            __syncthreads();
        }
        if (tid < 64) x_s[j0 + tid] *= LB[tid * 65];
        __syncthreads();
    }

    for (int j = tid; j < 1024; j += 256) g_sol[b * 1024 + j] = x_s[j];
}

// ---------------- GroupNorm(1, GR) + affine + SE scale ----------------
__global__ void __launch_bounds__(256) k_gn(const float* __restrict__ gn_g,
                                            const float* __restrict__ gn_b)
{
    int n = blockIdx.x, tid = threadIdx.x;
    __shared__ double s1[256], s2[256];
    double a = 0.0, c = 0.0;
    for (int idx = tid; idx < 4096; idx += 256) {
        double v = g_sol[n * 4096 + idx];
        a += v; c += v * v;
    }
    s1[tid] = a; s2[tid] = c;
    __syncthreads();
    for (int off = 128; off > 0; off >>= 1) {
        if (tid < off) { s1[tid] += s1[tid + off]; s2[tid] += s2[tid + off]; }
        __syncthreads();
    }
    double mu  = s1[0] * (1.0 / 4096.0);
    double var = s2[0] * (1.0 / 4096.0) - mu * mu;
    double invstd = rsqrt(var + 1e-5);
    for (int idx = tid; idx < 4096; idx += 256) {
        int g = idx >> 10;
        float v = (float)((g_sol[n * 4096 + idx] - mu) * invstd);
        v = v * gn_g[g] + gn_b[g];
        v *= g_se[n * 4 + g];
        g_ygn[n * 4096 + idx] = v;
    }
}

// ---------------- final conv: 4->128 3x3 ----------------
__global__ void __launch_bounds__(256) k_convf(
    const float* __restrict__ pw, const float* __restrict__ pb,
    float* __restrict__ out)
{
    int plane = blockIdx.x;          // 0..255
    int n  = plane >> 7;
    int co = plane & 127;
    __shared__ float ys[4 * 1156];
    for (int idx = threadIdx.x; idx < 4 * 1156; idx += 256) {
        int ci = idx / 1156, rr = idx - ci * 1156;
        int r = rr / 34, c = rr - r * 34;
        int gr = r - 1, gc = c - 1;
        ys[idx] = ((unsigned)gr < 32u && (unsigned)gc < 32u)
                  ? g_ygn[(n * 4 + ci) * 1024 + gr * 32 + gc] : 0.f;
    }
    __syncthreads();

    const float* wgt = pw + co * 36;
    float bias = pb[co];
    int row  = threadIdx.x >> 3;
    int col0 = (threadIdx.x & 7) << 2;
    float a0 = bias, a1 = bias, a2 = bias, a3 = bias;
#pragma unroll
    for (int ci = 0; ci < 4; ci++) {
        float w[9];
#pragma unroll
        for (int k = 0; k < 9; k++) w[k] = __ldg(wgt + ci * 9 + k);
        float s[3][6];
#pragma unroll
        for (int dy = 0; dy < 3; dy++)
#pragma unroll
            for (int dx = 0; dx < 6; dx++)
                s[dy][dx] = ys[ci * 1156 + (row + dy) * 34 + col0 + dx];
#pragma unroll
        for (int dy = 0; dy < 3; dy++) {
            float w0 = w[dy * 3], w1 = w[dy * 3 + 1], w2 = w[dy * 3 + 2];
            a0 += w0 * s[dy][0] + w1 * s[dy][1] + w2 * s[dy][2];
            a1 += w0 * s[dy][1] + w1 * s[dy][2] + w2 * s[dy][3];
            a2 += w0 * s[dy][2] + w1 * s[dy][3] + w2 * s[dy][4];
            a3 += w0 * s[dy][3] + w1 * s[dy][4] + w2 * s[dy][5];
        }
    }
    float* o = out + ((n * 128 + co) * 1024) + row * 32 + col0;
    o[0] = a0; o[1] = a1; o[2] = a2; o[3] = a3;
}

// ---------------- launcher ----------------
extern "C" void kernel_launch(void* const* d_in, const int* in_sizes, int n_in,
                              void* d_out, int out_size)
{
    const float* x    = (const float*)d_in[0];
    const float* a    = (const float*)d_in[1];
    const float* gw1  = (const float*)d_in[2];
    const float* gb1  = (const float*)d_in[3];
    const float* gw2  = (const float*)d_in[4];
    const float* gb2  = (const float*)d_in[5];
    const float* aw1  = (const float*)d_in[6];
    const float* ab1  = (const float*)d_in[7];
    const float* aw2  = (const float*)d_in[8];
    const float* ab2  = (const float*)d_in[9];
    const float* sw1  = (const float*)d_in[10];
    const float* sb1  = (const float*)d_in[11];
    const float* sw2  = (const float*)d_in[12];
    const float* sb2  = (const float*)d_in[13];
    const float* gn_g = (const float*)d_in[14];
    const float* gn_b = (const float*)d_in[15];
    const float* pw   = (const float*)d_in[16];
    const float* pb   = (const float*)d_in[17];
    float* out = (float*)d_out;

    k_conv1<<<256, 256>>>(x, gw1, gb1, aw1, ab1);
    k_conv2<<<96, 256>>>(gw2, gb2, aw2, ab2);
    k_se<<<2, 256>>>(x, sw1, sb1, sw2, sb2);
    k_build<<<32, 256>>>(a);
    k_solve<<<8, 256>>>();
    k_gn<<<2, 256>>>(gn_g, gn_b);
    k_convf<<<256, 256>>>(pw, pb, out);
}

// round 4
// speedup vs baseline: 4.7831x; 4.7831x over previous
#include <cuda_runtime.h>
#include <math.h>

// ---------------- scratch (static device allocations) ----------------
__device__ float g_band[8 * 1024 * 65];   // banded ATA -> L, [b][col][d], fp32
__device__ float g_atb[8 * 1024];         // rhs
__device__ float g_t[2 * 2 * 64 * 1024];  // conv1 outputs [branch][n][c][px]
__device__ float g_att[2 * 24 * 1024];    // sigmoid(conv2 att)
__device__ float g_grad[2 * 24 * 1024];   // conv2 grad
__device__ float g_se[2 * 4];
__device__ float g_sol[8 * 1024];
__device__ float g_ygn[2 * 4 * 1024];

// ---------------- conv1: 64->64 3x3, lrelu, both branches ----------------
__global__ void __launch_bounds__(256) k_conv1(
    const float* __restrict__ x,
    const float* __restrict__ gw1, const float* __restrict__ gb1,
    const float* __restrict__ aw1, const float* __restrict__ ab1)
{
    int plane  = blockIdx.x;           // 0..255
    int branch = plane >> 7;           // 0=grad, 1=att
    int n      = (plane >> 6) & 1;
    int co     = plane & 63;
    const float* wgt  = (branch ? aw1 : gw1) + co * 576;
    float bias        = (branch ? ab1 : gb1)[co];

    __shared__ float xs[34 * 34];
    int row  = threadIdx.x >> 3;        // 0..31
    int col0 = (threadIdx.x & 7) << 2;  // 0..28 step 4

    float a0 = bias, a1 = bias, a2 = bias, a3 = bias;
    const float* xbase = x + n * 64 * 1024;

    for (int ci = 0; ci < 64; ci++) {
        __syncthreads();
        const float* xp = xbase + ci * 1024;
        for (int idx = threadIdx.x; idx < 1156; idx += 256) {
            int r = idx / 34, c = idx - r * 34;
            int gr = r - 1, gc = c - 1;
            xs[idx] = ((unsigned)gr < 32u && (unsigned)gc < 32u) ? xp[gr * 32 + gc] : 0.f;
        }
        __syncthreads();
        float w[9];
#pragma unroll
        for (int k = 0; k < 9; k++) w[k] = __ldg(wgt + ci * 9 + k);
        float s[3][6];
#pragma unroll
        for (int dy = 0; dy < 3; dy++)
#pragma unroll
            for (int dx = 0; dx < 6; dx++)
                s[dy][dx] = xs[(row + dy) * 34 + col0 + dx];
#pragma unroll
        for (int dy = 0; dy < 3; dy++) {
            float w0 = w[dy * 3], w1 = w[dy * 3 + 1], w2 = w[dy * 3 + 2];
            a0 += w0 * s[dy][0] + w1 * s[dy][1] + w2 * s[dy][2];
            a1 += w0 * s[dy][1] + w1 * s[dy][2] + w2 * s[dy][3];
            a2 += w0 * s[dy][2] + w1 * s[dy][3] + w2 * s[dy][4];
            a3 += w0 * s[dy][3] + w1 * s[dy][4] + w2 * s[dy][5];
        }
    }
    float* out = g_t + (((branch * 2 + n) * 64 + co) * 1024) + row * 32 + col0;
    out[0] = a0 > 0.f ? a0 : 0.01f * a0;
    out[1] = a1 > 0.f ? a1 : 0.01f * a1;
    out[2] = a2 > 0.f ? a2 : 0.01f * a2;
    out[3] = a3 > 0.f ? a3 : 0.01f * a3;
}

// ---------------- conv2: 64->24 3x3 (+sigmoid on att branch) ----------------
__global__ void __launch_bounds__(256) k_conv2(
    const float* __restrict__ gw2, const float* __restrict__ gb2,
    const float* __restrict__ aw2, const float* __restrict__ ab2)
{
    int plane  = blockIdx.x;            // 0..95
    int branch = plane / 48;
    int rem    = plane - branch * 48;
    int n      = rem / 24;
    int co     = rem - n * 24;
    const float* wgt = (branch ? aw2 : gw2) + co * 576;
    float bias       = (branch ? ab2 : gb2)[co];

    __shared__ float xs[34 * 34];
    int row  = threadIdx.x >> 3;
    int col0 = (threadIdx.x & 7) << 2;

    float a0 = bias, a1 = bias, a2 = bias, a3 = bias;
    const float* xbase = g_t + (branch * 2 + n) * 64 * 1024;

    for (int ci = 0; ci < 64; ci++) {
        __syncthreads();
        const float* xp = xbase + ci * 1024;
        for (int idx = threadIdx.x; idx < 1156; idx += 256) {
            int r = idx / 34, c = idx - r * 34;
            int gr = r - 1, gc = c - 1;
            xs[idx] = ((unsigned)gr < 32u && (unsigned)gc < 32u) ? xp[gr * 32 + gc] : 0.f;
        }
        __syncthreads();
        float w[9];
#pragma unroll
        for (int k = 0; k < 9; k++) w[k] = __ldg(wgt + ci * 9 + k);
        float s[3][6];
#pragma unroll
        for (int dy = 0; dy < 3; dy++)
#pragma unroll
            for (int dx = 0; dx < 6; dx++)
                s[dy][dx] = xs[(row + dy) * 34 + col0 + dx];
#pragma unroll
        for (int dy = 0; dy < 3; dy++) {
            float w0 = w[dy * 3], w1 = w[dy * 3 + 1], w2 = w[dy * 3 + 2];
            a0 += w0 * s[dy][0] + w1 * s[dy][1] + w2 * s[dy][2];
            a1 += w0 * s[dy][1] + w1 * s[dy][2] + w2 * s[dy][3];
            a2 += w0 * s[dy][2] + w1 * s[dy][3] + w2 * s[dy][4];
            a3 += w0 * s[dy][3] + w1 * s[dy][4] + w2 * s[dy][5];
        }
    }
    float* out = (branch ? g_att : g_grad) + ((n * 24 + co) * 1024) + row * 32 + col0;
    if (branch) {
        out[0] = 1.f / (1.f + expf(-a0));
        out[1] = 1.f / (1.f + expf(-a1));
        out[2] = 1.f / (1.f + expf(-a2));
        out[3] = 1.f / (1.f + expf(-a3));
    } else {
        out[0] = a0; out[1] = a1; out[2] = a2; out[3] = a3;
    }
}

// ---------------- SE branch ----------------
__global__ void __launch_bounds__(256) k_se(
    const float* __restrict__ x,
    const float* __restrict__ sw1, const float* __restrict__ sb1,
    const float* __restrict__ sw2, const float* __restrict__ sb2)
{
    int n = blockIdx.x, tid = threadIdx.x;
    __shared__ float red[256];
    __shared__ float pooled[64];
    __shared__ float s1[32];

    int c = tid >> 2, part = tid & 3;
    const float* xp = x + (n * 64 + c) * 1024 + part * 256;
    float s = 0.f;
    for (int i = 0; i < 256; i++) s += xp[i];
    red[tid] = s;
    __syncthreads();
    if (part == 0)
        pooled[c] = (red[tid] + red[tid + 1] + red[tid + 2] + red[tid + 3]) * (1.f / 1024.f);
    __syncthreads();
    if (tid < 32) {
        float a = sb1[tid];
        for (int j = 0; j < 64; j++) a += sw1[tid * 64 + j] * pooled[j];
        s1[tid] = a > 0.f ? a : 0.01f * a;
    }
    __syncthreads();
    if (tid < 4) {
        float a = sb2[tid];
        for (int j = 0; j < 32; j++) a += sw2[tid * 32 + j] * s1[j];
        g_se[n * 4 + tid] = 1.f / (1.f + expf(-a));
    }
}

// ---------------- build banded ATA + ATB: deterministic gather ----------------
__global__ void __launch_bounds__(256) k_build(const float* __restrict__ a)
{
    int t = blockIdx.x * blockDim.x + threadIdx.x;   // 0..8191
    int b = t >> 10;
    int q = t & 1023;
    int n = b >> 2;
    int g = b & 3;
    const int offs[7] = {0, 1, 2, 31, 32, 33, 64};

    float acc[11];
    const int DVALS[11] = {0, 1, 2, 29, 30, 31, 32, 33, 62, 63, 64};
#pragma unroll
    for (int z = 0; z < 11; z++) acc[z] = 0.f;
    acc[0] = 1e-12f;
    float atb = 0.f;

#pragma unroll
    for (int k = 0; k < 6; k++) {
        int ch = g * 6 + k;
        const float* attp  = g_att  + (n * 24 + ch) * 1024;
        const float* gradp = g_grad + (n * 24 + ch) * 1024;
#pragma unroll
        for (int c2 = 0; c2 < 7; c2++) {
            int i = q - offs[c2];
            if (i >= 0) {
                float attv = attp[i];
                float at2  = attv * attv;
                const float* arow = a + (size_t)(i * 6 + k) * 1024;
                float v2 = arow[q];
                if (v2 != 0.f) {
                    atb += v2 * at2 * gradp[i];
                    float w2 = v2 * at2;
#pragma unroll
                    for (int c1 = c2; c1 < 7; c1++) {
                        int col1 = i + offs[c1];
                        if (col1 <= 1023) {
                            float contrib = arow[col1] * w2;
                            int d = offs[c1] - offs[c2];
#pragma unroll
                            for (int z = 0; z < 11; z++)
                                if (DVALS[z] == d) acc[z] += contrib;
                        }
                    }
                }
            }
        }
    }

    float* bc = g_band + ((size_t)b * 1024 + q) * 65;
#pragma unroll
    for (int d = 0; d < 65; d++) {
        float v = 0.f;
#pragma unroll
        for (int z = 0; z < 11; z++)
            if (DVALS[z] == d) v = acc[z];
        bc[d] = v;
    }
    g_atb[b * 1024 + q] = atb;
}

// ---------------- banded Cholesky, fp32 smem window, 1 barrier/step ----------
// Window W: unscaled band columns, slot = col % 65. Per step j:
//  - all threads read pivot inv from smem (published last step by pair (1,1))
//  - tid 1..64: write L column to gmem, forward-sub rhs, commit prefetched
//    column j+64 entries 1..64
//  - tid 0: diag writeout, x_s[j], commit entry 0 fused with pair (64,64)
//  - 2079 generic rank-1 pairs (p<=63 or q<64) streamed tid-strided;
//    pair (1,1) also publishes rsqrt of next pivot diag
//  - register FIFO P0..P3 prefetches gmem columns 4 steps ahead
__global__ void __launch_bounds__(256) k_solve()
{
    int b   = blockIdx.x;
    int tid = threadIdx.x;
    float* band = g_band + (size_t)b * 1024 * 65;

    __shared__ float W[65 * 65];
    __shared__ float y_s[1100];          // padded: fwd-sub writes up to j+64
    __shared__ float x_s[1024];
    __shared__ unsigned short PQ[2080];  // p-major pairs; last (64,64) unused
    __shared__ float s_inv[2];

    // pair table (p,q), 1<=p<=q<=64, p-major
    {
        int base = 0;
        for (int p = 1; p <= 64; p++) {
            int len = 65 - p;
            for (int o = tid; o < len; o += 256)
                PQ[base + o] = (unsigned short)(p | ((p + o) << 8));
            base += len;
        }
    }

    for (int j = tid; j < 1024; j += 256) y_s[j] = g_atb[b * 1024 + j];
    for (int j = 1024 + tid; j < 1100; j += 256) y_s[j] = 0.f;
    for (int idx = tid; idx < 64 * 65; idx += 256) W[idx] = band[idx];

    float P0 = 0.f, P1 = 0.f, P2 = 0.f, P3 = 0.f;
    if (tid < 65) {
        P0 = band[64 * 65 + tid];
        P1 = band[65 * 65 + tid];
        P2 = band[66 * 65 + tid];
        P3 = band[67 * 65 + tid];
    }
    __syncthreads();
    if (tid == 0) {
        float d0 = W[0];
        float r = rsqrtf(d0);
        s_inv[0] = r * (1.5f - 0.5f * d0 * r * r);
    }
    __syncthreads();

    for (int j = 0; j < 1024; j++) {
        int slot = j % 65;
        const float* Wp = W + slot * 65;
        float inv  = s_inv[j & 1];
        float inv2 = inv * inv;
        int cslot = slot + 64; if (cslot >= 65) cslot -= 65;
        bool have_in = (j + 64 <= 1023);

        if (tid > 0 && tid < 65) {
            float wv = Wp[tid];
            float Lr = wv * inv;
            band[j * 65 + tid] = Lr;                 // L write-out
            y_s[j + tid] -= Lr * (y_s[j] * inv);     // forward-sub
            if (have_in) W[cslot * 65 + tid] = P0;   // commit entries 1..64
        } else if (tid == 0) {
            band[j * 65] = inv;                      // store INVERSE diag
            x_s[j] = y_s[j] * inv;
            if (have_in) {
                float lq = Wp[64];
                W[cslot * 65] = P0 - lq * lq * inv2; // commit d=0 + pair(64,64)
            }
        }

        for (int idx2 = tid; idx2 < 2079; idx2 += 256) {
            int pq = PQ[idx2];
            int p = pq & 255, q = pq >> 8;
            float lq = Wp[q];
            float lp = Wp[p];
            int ds = slot + p; if (ds >= 65) ds -= 65;
            float nv = W[ds * 65 + (q - p)] - lq * lp * inv2;
            W[ds * 65 + (q - p)] = nv;
            if (idx2 == 0) {                         // pair (1,1): next diag
                float r = rsqrtf(nv);
                s_inv[(j + 1) & 1] = r * (1.5f - 0.5f * nv * r * r);
            }
        }

        if (tid < 65) {                              // shift prefetch FIFO
            P0 = P1; P1 = P2; P2 = P3;
            int c = j + 68;
            P3 = (c <= 1023) ? band[c * 65 + tid] : 0.f;
        }
        __syncthreads();
    }

    // ---- back substitution: L^T x = y', blocked by 64 rows (reuse W as LB) --
    float* LB = W;
    for (int blk = 15; blk >= 0; blk--) {
        int j0 = blk * 64;
        for (int idx = tid; idx < 64 * 65; idx += 256)
            LB[idx] = band[j0 * 65 + idx];
        __syncthreads();
        if (tid < 64) {
            int t = tid, jj = j0 + t;
            float s = 0.f;
            for (int r = 64 - t; r <= 64; r++) {
                int jr = jj + r;
                if (jr < 1024) s += LB[t * 65 + r] * x_s[jr];
            }
            x_s[jj] -= s;
        }
        __syncthreads();
        for (int t = 63; t >= 1; t--) {
            float xval = x_s[j0 + t] * LB[t * 65];
            if (tid < t) x_s[j0 + tid] -= LB[tid * 65 + (t - tid)] * xval;
            __syncthreads();
        }
        if (tid < 64) x_s[j0 + tid] *= LB[tid * 65];
        __syncthreads();
    }

    for (int j = tid; j < 1024; j += 256) g_sol[b * 1024 + j] = x_s[j];
}

// ---------------- GroupNorm(1, GR) + affine + SE scale ----------------
__global__ void __launch_bounds__(256) k_gn(const float* __restrict__ gn_g,
                                            const float* __restrict__ gn_b)
{
    int n = blockIdx.x, tid = threadIdx.x;
    __shared__ double s1[256], s2[256];
    double a = 0.0, c = 0.0;
    for (int idx = tid; idx < 4096; idx += 256) {
        double v = g_sol[n * 4096 + idx];
        a += v; c += v * v;
    }
    s1[tid] = a; s2[tid] = c;
    __syncthreads();
    for (int off = 128; off > 0; off >>= 1) {
        if (tid < off) { s1[tid] += s1[tid + off]; s2[tid] += s2[tid + off]; }
        __syncthreads();
    }
    double mu  = s1[0] * (1.0 / 4096.0);
    double var = s2[0] * (1.0 / 4096.0) - mu * mu;
    double invstd = rsqrt(var + 1e-5);
    for (int idx = tid; idx < 4096; idx += 256) {
        int g = idx >> 10;
        float v = (float)((g_sol[n * 4096 + idx] - mu) * invstd);
        v = v * gn_g[g] + gn_b[g];
        v *= g_se[n * 4 + g];
        g_ygn[n * 4096 + idx] = v;
    }
}

// ---------------- final conv: 4->128 3x3 ----------------
__global__ void __launch_bounds__(256) k_convf(
    const float* __restrict__ pw, const float* __restrict__ pb,
    float* __restrict__ out)
{
    int plane = blockIdx.x;          // 0..255
    int n  = plane >> 7;
    int co = plane & 127;
    __shared__ float ys[4 * 1156];
    for (int idx = threadIdx.x; idx < 4 * 1156; idx += 256) {
        int ci = idx / 1156, rr = idx - ci * 1156;
        int r = rr / 34, c = rr - r * 34;
        int gr = r - 1, gc = c - 1;
        ys[idx] = ((unsigned)gr < 32u && (unsigned)gc < 32u)
                  ? g_ygn[(n * 4 + ci) * 1024 + gr * 32 + gc] : 0.f;
    }
    __syncthreads();

    const float* wgt = pw + co * 36;
    float bias = pb[co];
    int row  = threadIdx.x >> 3;
    int col0 = (threadIdx.x & 7) << 2;
    float a0 = bias, a1 = bias, a2 = bias, a3 = bias;
#pragma unroll
    for (int ci = 0; ci < 4; ci++) {
        float w[9];
#pragma unroll
        for (int k = 0; k < 9; k++) w[k] = __ldg(wgt + ci * 9 + k);
        float s[3][6];
#pragma unroll
        for (int dy = 0; dy < 3; dy++)
#pragma unroll
            for (int dx = 0; dx < 6; dx++)
                s[dy][dx] = ys[ci * 1156 + (row + dy) * 34 + col0 + dx];
#pragma unroll
        for (int dy = 0; dy < 3; dy++) {
            float w0 = w[dy * 3], w1 = w[dy * 3 + 1], w2 = w[dy * 3 + 2];
            a0 += w0 * s[dy][0] + w1 * s[dy][1] + w2 * s[dy][2];
            a1 += w0 * s[dy][1] + w1 * s[dy][2] + w2 * s[dy][3];
            a2 += w0 * s[dy][2] + w1 * s[dy][3] + w2 * s[dy][4];
            a3 += w0 * s[dy][3] + w1 * s[dy][4] + w2 * s[dy][5];
        }
    }
    float* o = out + ((n * 128 + co) * 1024) + row * 32 + col0;
    o[0] = a0; o[1] = a1; o[2] = a2; o[3] = a3;
}

// ---------------- launcher ----------------
extern "C" void kernel_launch(void* const* d_in, const int* in_sizes, int n_in,
                              void* d_out, int out_size)
{
    const float* x    = (const float*)d_in[0];
    const float* a    = (const float*)d_in[1];
    const float* gw1  = (const float*)d_in[2];
    const float* gb1  = (const float*)d_in[3];
    const float* gw2  = (const float*)d_in[4];
    const float* gb2  = (const float*)d_in[5];
    const float* aw1  = (const float*)d_in[6];
    const float* ab1  = (const float*)d_in[7];
    const float* aw2  = (const float*)d_in[8];
    const float* ab2  = (const float*)d_in[9];
    const float* sw1  = (const float*)d_in[10];
    const float* sb1  = (const float*)d_in[11];
    const float* sw2  = (const float*)d_in[12];
    const float* sb2  = (const float*)d_in[13];
    const float* gn_g = (const float*)d_in[14];
    const float* gn_b = (const float*)d_in[15];
    const float* pw   = (const float*)d_in[16];
    const float* pb   = (const float*)d_in[17];
    float* out = (float*)d_out;

    k_conv1<<<256, 256>>>(x, gw1, gb1, aw1, ab1);
    k_conv2<<<96, 256>>>(gw2, gb2, aw2, ab2);
    k_se<<<2, 256>>>(x, sw1, sb1, sw2, sb2);
    k_build<<<32, 256>>>(a);
    k_solve<<<8, 256>>>();
    k_gn<<<2, 256>>>(gn_g, gn_b);
    k_convf<<<256, 256>>>(pw, pb, out);
}

// round 5
// speedup vs baseline: 7.2086x; 1.5071x over previous
#include <cuda_runtime.h>
#include <math.h>

// ---------------- scratch (static device allocations) ----------------
__device__ float g_band[8 * 1024 * 65];   // banded ATA -> L, [b][col][d], fp32
__device__ float g_atb[8 * 1024];         // rhs
__device__ float g_t[2 * 2 * 64 * 1024];  // conv1 outputs [branch][n][c][px]
__device__ float g_att[2 * 24 * 1024];    // sigmoid(conv2 att)
__device__ float g_grad[2 * 24 * 1024];   // conv2 grad
__device__ float g_se[2 * 4];
__device__ float g_sol[8 * 1024];
__device__ float g_ygn[2 * 4 * 1024];

// ---------------- conv1: 64->64 3x3, lrelu, both branches ----------------
__global__ void __launch_bounds__(256) k_conv1(
    const float* __restrict__ x,
    const float* __restrict__ gw1, const float* __restrict__ gb1,
    const float* __restrict__ aw1, const float* __restrict__ ab1)
{
    int plane  = blockIdx.x;           // 0..255
    int branch = plane >> 7;           // 0=grad, 1=att
    int n      = (plane >> 6) & 1;
    int co     = plane & 63;
    const float* wgt  = (branch ? aw1 : gw1) + co * 576;
    float bias        = (branch ? ab1 : gb1)[co];

    __shared__ float xs[34 * 34];
    int row  = threadIdx.x >> 3;        // 0..31
    int col0 = (threadIdx.x & 7) << 2;  // 0..28 step 4

    float a0 = bias, a1 = bias, a2 = bias, a3 = bias;
    const float* xbase = x + n * 64 * 1024;

    for (int ci = 0; ci < 64; ci++) {
        __syncthreads();
        const float* xp = xbase + ci * 1024;
        for (int idx = threadIdx.x; idx < 1156; idx += 256) {
            int r = idx / 34, c = idx - r * 34;
            int gr = r - 1, gc = c - 1;
            xs[idx] = ((unsigned)gr < 32u && (unsigned)gc < 32u) ? xp[gr * 32 + gc] : 0.f;
        }
        __syncthreads();
        float w[9];
#pragma unroll
        for (int k = 0; k < 9; k++) w[k] = __ldg(wgt + ci * 9 + k);
        float s[3][6];
#pragma unroll
        for (int dy = 0; dy < 3; dy++)
#pragma unroll
            for (int dx = 0; dx < 6; dx++)
                s[dy][dx] = xs[(row + dy) * 34 + col0 + dx];
#pragma unroll
        for (int dy = 0; dy < 3; dy++) {
            float w0 = w[dy * 3], w1 = w[dy * 3 + 1], w2 = w[dy * 3 + 2];
            a0 += w0 * s[dy][0] + w1 * s[dy][1] + w2 * s[dy][2];
            a1 += w0 * s[dy][1] + w1 * s[dy][2] + w2 * s[dy][3];
            a2 += w0 * s[dy][2] + w1 * s[dy][3] + w2 * s[dy][4];
            a3 += w0 * s[dy][3] + w1 * s[dy][4] + w2 * s[dy][5];
        }
    }
    float* out = g_t + (((branch * 2 + n) * 64 + co) * 1024) + row * 32 + col0;
    out[0] = a0 > 0.f ? a0 : 0.01f * a0;
    out[1] = a1 > 0.f ? a1 : 0.01f * a1;
    out[2] = a2 > 0.f ? a2 : 0.01f * a2;
    out[3] = a3 > 0.f ? a3 : 0.01f * a3;
}

// ---------------- conv2: 64->24 3x3 (+sigmoid on att branch) ----------------
__global__ void __launch_bounds__(256) k_conv2(
    const float* __restrict__ gw2, const float* __restrict__ gb2,
    const float* __restrict__ aw2, const float* __restrict__ ab2)
{
    int plane  = blockIdx.x;            // 0..95
    int branch = plane / 48;
    int rem    = plane - branch * 48;
    int n      = rem / 24;
    int co     = rem - n * 24;
    const float* wgt = (branch ? aw2 : gw2) + co * 576;
    float bias       = (branch ? ab2 : gb2)[co];

    __shared__ float xs[34 * 34];
    int row  = threadIdx.x >> 3;
    int col0 = (threadIdx.x & 7) << 2;

    float a0 = bias, a1 = bias, a2 = bias, a3 = bias;
    const float* xbase = g_t + (branch * 2 + n) * 64 * 1024;

    for (int ci = 0; ci < 64; ci++) {
        __syncthreads();
        const float* xp = xbase + ci * 1024;
        for (int idx = threadIdx.x; idx < 1156; idx += 256) {
            int r = idx / 34, c = idx - r * 34;
            int gr = r - 1, gc = c - 1;
            xs[idx] = ((unsigned)gr < 32u && (unsigned)gc < 32u) ? xp[gr * 32 + gc] : 0.f;
        }
        __syncthreads();
        float w[9];
#pragma unroll
        for (int k = 0; k < 9; k++) w[k] = __ldg(wgt + ci * 9 + k);
        float s[3][6];
#pragma unroll
        for (int dy = 0; dy < 3; dy++)
#pragma unroll
            for (int dx = 0; dx < 6; dx++)
                s[dy][dx] = xs[(row + dy) * 34 + col0 + dx];
#pragma unroll
        for (int dy = 0; dy < 3; dy++) {
            float w0 = w[dy * 3], w1 = w[dy * 3 + 1], w2 = w[dy * 3 + 2];
            a0 += w0 * s[dy][0] + w1 * s[dy][1] + w2 * s[dy][2];
            a1 += w0 * s[dy][1] + w1 * s[dy][2] + w2 * s[dy][3];
            a2 += w0 * s[dy][2] + w1 * s[dy][3] + w2 * s[dy][4];
            a3 += w0 * s[dy][3] + w1 * s[dy][4] + w2 * s[dy][5];
        }
    }
    float* out = (branch ? g_att : g_grad) + ((n * 24 + co) * 1024) + row * 32 + col0;
    if (branch) {
        out[0] = 1.f / (1.f + expf(-a0));
        out[1] = 1.f / (1.f + expf(-a1));
        out[2] = 1.f / (1.f + expf(-a2));
        out[3] = 1.f / (1.f + expf(-a3));
    } else {
        out[0] = a0; out[1] = a1; out[2] = a2; out[3] = a3;
    }
}

// ---------------- SE branch ----------------
__global__ void __launch_bounds__(256) k_se(
    const float* __restrict__ x,
    const float* __restrict__ sw1, const float* __restrict__ sb1,
    const float* __restrict__ sw2, const float* __restrict__ sb2)
{
    int n = blockIdx.x, tid = threadIdx.x;
    __shared__ float red[256];
    __shared__ float pooled[64];
    __shared__ float s1[32];

    int c = tid >> 2, part = tid & 3;
    const float* xp = x + (n * 64 + c) * 1024 + part * 256;
    float s = 0.f;
    for (int i = 0; i < 256; i++) s += xp[i];
    red[tid] = s;
    __syncthreads();
    if (part == 0)
        pooled[c] = (red[tid] + red[tid + 1] + red[tid + 2] + red[tid + 3]) * (1.f / 1024.f);
    __syncthreads();
    if (tid < 32) {
        float a = sb1[tid];
        for (int j = 0; j < 64; j++) a += sw1[tid * 64 + j] * pooled[j];
        s1[tid] = a > 0.f ? a : 0.01f * a;
    }
    __syncthreads();
    if (tid < 4) {
        float a = sb2[tid];
        for (int j = 0; j < 32; j++) a += sw2[tid * 32 + j] * s1[j];
        g_se[n * 4 + tid] = 1.f / (1.f + expf(-a));
    }
}

// ---------------- build banded ATA + ATB: deterministic gather ----------------
__global__ void __launch_bounds__(256) k_build(const float* __restrict__ a)
{
    int t = blockIdx.x * blockDim.x + threadIdx.x;   // 0..8191
    int b = t >> 10;
    int q = t & 1023;
    int n = b >> 2;
    int g = b & 3;
    const int offs[7] = {0, 1, 2, 31, 32, 33, 64};

    float acc[11];
    const int DVALS[11] = {0, 1, 2, 29, 30, 31, 32, 33, 62, 63, 64};
#pragma unroll
    for (int z = 0; z < 11; z++) acc[z] = 0.f;
    acc[0] = 1e-12f;
    float atb = 0.f;

#pragma unroll
    for (int k = 0; k < 6; k++) {
        int ch = g * 6 + k;
        const float* attp  = g_att  + (n * 24 + ch) * 1024;
        const float* gradp = g_grad + (n * 24 + ch) * 1024;
#pragma unroll
        for (int c2 = 0; c2 < 7; c2++) {
            int i = q - offs[c2];
            if (i >= 0) {
                float attv = attp[i];
                float at2  = attv * attv;
                const float* arow = a + (size_t)(i * 6 + k) * 1024;
                float v2 = arow[q];
                if (v2 != 0.f) {
                    atb += v2 * at2 * gradp[i];
                    float w2 = v2 * at2;
#pragma unroll
                    for (int c1 = c2; c1 < 7; c1++) {
                        int col1 = i + offs[c1];
                        if (col1 <= 1023) {
                            float contrib = arow[col1] * w2;
                            int d = offs[c1] - offs[c2];
#pragma unroll
                            for (int z = 0; z < 11; z++)
                                if (DVALS[z] == d) acc[z] += contrib;
                        }
                    }
                }
            }
        }
    }

    float* bc = g_band + ((size_t)b * 1024 + q) * 65;
#pragma unroll
    for (int d = 0; d < 65; d++) {
        float v = 0.f;
#pragma unroll
        for (int z = 0; z < 11; z++)
            if (DVALS[z] == d) v = acc[z];
        bc[d] = v;
    }
    g_atb[b * 1024 + q] = atb;
}

// ---------------- banded Cholesky, fp32, static pairs + incremental addrs ----
// Thread pair ownership: flat p-major list of the 2079 pairs (p,q), 1<=p<=q<=64
// excluding (64,64). Thread t owns pairs t, t+256, ..., t+1792 (8 each) in
// scalar registers; pairs 2048..2078 are a 9th pair for threads 0..30.
// Ring window W[65][65] (slot = col % 65); RMW address per pair kept as an
// incremental register (+65, wrap at 4225). Pivot column is published each
// step into a fixed double-buffer Lsm[2][66] by the p==1 pair owners (threads
// 0..63, first pair) + thread 190 (d=64 entry, never updated after commit).
// Threads 191..255 handle diag/L-writeout/forward-sub/commit/prefetch FIFO.
// One __syncthreads per column step.
__global__ void __launch_bounds__(256) k_solve()
{
    int b   = blockIdx.x;
    int tid = threadIdx.x;
    float* band = g_band + (size_t)b * 1024 * 65;

    __shared__ float W[65 * 65];
    __shared__ float y_s[1100];
    __shared__ float x_s[1024];
    __shared__ float Lsm[2 * 66];
    __shared__ float s_inv[2];

    // ---- decode 8 static pairs into scalar registers ----
#define DECODE(IDX, PP, QQ, AA) {                       \
        int _i = (IDX); int _p = 1, _b = 0;             \
        while (_i >= _b + 65 - _p) { _b += 65 - _p; _p++; } \
        int _q = _p + (_i - _b);                        \
        PP = _p; QQ = _q; AA = _p * 65 + (_q - _p); }
    int p0,q0,a0, p1,q1,a1, p2,q2,a2, p3,q3,a3;
    int p4,q4,a4, p5,q5,a5, p6,q6,a6, p7,q7,a7;
    DECODE(tid,        p0,q0,a0)
    DECODE(tid + 256,  p1,q1,a1)
    DECODE(tid + 512,  p2,q2,a2)
    DECODE(tid + 768,  p3,q3,a3)
    DECODE(tid + 1024, p4,q4,a4)
    DECODE(tid + 1280, p5,q5,a5)
    DECODE(tid + 1536, p6,q6,a6)
    DECODE(tid + 1792, p7,q7,a7)
    bool has9 = (tid < 31);
    int p8 = 1, q8 = 1, a8 = 4224;   // default: harmless self-RMW slot
    if (has9) DECODE(2048 + tid, p8,q8,a8)
#undef DECODE

    // ---- role registers (threads 191..255) ----
    int r   = tid - 191;             // 0..64 valid only for tid>=191
    int lw  = r;                     // band L write addr
    int cm  = 4160 + r;              // commit addr in W (col 64 slot)
    int pf  = 4420 + r;              // prefetch gmem addr (col 68)
    float P0 = 0.f, P1 = 0.f, P2 = 0.f, P3 = 0.f;
    int a65 = 129;                   // thread 190: W addr of (col j+1, d=64)

    // ---- init loads ----
    for (int j = tid; j < 1024; j += 256) y_s[j] = g_atb[b * 1024 + j];
    for (int j = 1024 + tid; j < 1100; j += 256) y_s[j] = 0.f;
    for (int idx = tid; idx < 64 * 65; idx += 256) W[idx] = band[idx];
    if (tid >= 191) {
        P0 = band[64 * 65 + r];
        P1 = band[65 * 65 + r];
        P2 = band[66 * 65 + r];
        P3 = band[67 * 65 + r];
    }
    __syncthreads();
    if (tid >= 191) {
        Lsm[r] = W[r];               // publish column 0
        if (r == 0) {
            float d0 = W[0];
            float rr = rsqrtf(d0);
            s_inv[0] = rr * (1.5f - 0.5f * d0 * rr * rr);
        }
    }
    __syncthreads();

    // ---- main factorization loop: 1 barrier per column ----
    for (int j = 0; j < 1024; j++) {
        int bb = j & 1;
        int nb = bb ^ 1;
        const float* Lb = Lsm + bb * 66;
        float inv  = s_inv[bb];
        float inv2 = inv * inv;
        bool have_in = (j < 960);

#define PAIR(PP, QQ, AA) {                              \
        float _lp = Lb[PP], _lq = Lb[QQ];               \
        float _nv = W[AA] - _lp * _lq * inv2;           \
        W[AA] = _nv;                                    \
        AA += 65; if (AA >= 4225) AA -= 4225; }

        // first pair: p==1 owners (tid<64) publish column j+1
        {
            float _lp = Lb[p0], _lq = Lb[q0];
            float _nv = W[a0] - _lp * _lq * inv2;
            W[a0] = _nv;
            a0 += 65; if (a0 >= 4225) a0 -= 4225;
            if (tid < 64) {
                Lsm[nb * 66 + tid] = _nv;    // col j+1, d = tid (q-1)
                if (tid == 0) {
                    float rr = rsqrtf(_nv);
                    s_inv[nb] = rr * (1.5f - 0.5f * _nv * rr * rr);
                }
            }
        }
        PAIR(p1,q1,a1)
        PAIR(p2,q2,a2)
        PAIR(p3,q3,a3)
        PAIR(p4,q4,a4)
        PAIR(p5,q5,a5)
        PAIR(p6,q6,a6)
        PAIR(p7,q7,a7)
        if (has9) {
            float _lp = Lb[p8], _lq = Lb[q8];
            W[a8] -= _lp * _lq * inv2;
            a8 += 65; if (a8 >= 4225) a8 -= 4225;
        }
#undef PAIR

        if (tid == 190) {                    // col j+1, d=64 (final at commit)
            Lsm[nb * 66 + 64] = W[a65];
            a65 += 65; if (a65 >= 4225) a65 -= 4225;
        }

        if (tid >= 191) {
            if (r == 0) {
                band[lw] = inv;              // store INVERSE diag
                x_s[j] = y_s[j] * inv;
                if (have_in) {
                    float l64 = Lb[64];
                    W[cm] = P0 - l64 * l64 * inv2;  // commit d=0 + pair(64,64)
                }
            } else {
                float wv = Lb[r];
                float Lr = wv * inv;
                band[lw] = Lr;               // L write-out
                y_s[j + r] -= Lr * (y_s[j] * inv);  // forward-sub
                if (have_in) W[cm] = P0;     // commit entries 1..64
            }
            P0 = P1; P1 = P2; P2 = P3;
            P3 = (pf < 66560) ? band[pf] : 0.f;
            pf += 65;
            cm += 65; if (cm >= 4225) cm -= 4225;
            lw += 65;
        }
        __syncthreads();
    }

    // ---- back substitution: L^T x = y', blocked by 64 rows (reuse W) ----
    float* LB = W;
    for (int blk = 15; blk >= 0; blk--) {
        int j0 = blk * 64;
        for (int idx = tid; idx < 64 * 65; idx += 256)
            LB[idx] = band[j0 * 65 + idx];
        __syncthreads();
        if (tid < 64) {
            int t = tid, jj = j0 + t;
            float s = 0.f;
            for (int rr = 64 - t; rr <= 64; rr++) {
                int jr = jj + rr;
                if (jr < 1024) s += LB[t * 65 + rr] * x_s[jr];
            }
            x_s[jj] -= s;
        }
        __syncthreads();
        for (int t = 63; t >= 1; t--) {
            float xval = x_s[j0 + t] * LB[t * 65];
            if (tid < t) x_s[j0 + tid] -= LB[tid * 65 + (t - tid)] * xval;
            __syncthreads();
        }
        if (tid < 64) x_s[j0 + tid] *= LB[tid * 65];
        __syncthreads();
    }

    for (int j = tid; j < 1024; j += 256) g_sol[b * 1024 + j] = x_s[j];
}

// ---------------- GroupNorm(1, GR) + affine + SE scale ----------------
__global__ void __launch_bounds__(256) k_gn(const float* __restrict__ gn_g,
                                            const float* __restrict__ gn_b)
{
    int n = blockIdx.x, tid = threadIdx.x;
    __shared__ double s1[256], s2[256];
    double a = 0.0, c = 0.0;
    for (int idx = tid; idx < 4096; idx += 256) {
        double v = g_sol[n * 4096 + idx];
        a += v; c += v * v;
    }
    s1[tid] = a; s2[tid] = c;
    __syncthreads();
    for (int off = 128; off > 0; off >>= 1) {
        if (tid < off) { s1[tid] += s1[tid + off]; s2[tid] += s2[tid + off]; }
        __syncthreads();
    }
    double mu  = s1[0] * (1.0 / 4096.0);
    double var = s2[0] * (1.0 / 4096.0) - mu * mu;
    double invstd = rsqrt(var + 1e-5);
    for (int idx = tid; idx < 4096; idx += 256) {
        int g = idx >> 10;
        float v = (float)((g_sol[n * 4096 + idx] - mu) * invstd);
        v = v * gn_g[g] + gn_b[g];
        v *= g_se[n * 4 + g];
        g_ygn[n * 4096 + idx] = v;
    }
}

// ---------------- final conv: 4->128 3x3 ----------------
__global__ void __launch_bounds__(256) k_convf(
    const float* __restrict__ pw, const float* __restrict__ pb,
    float* __restrict__ out)
{
    int plane = blockIdx.x;          // 0..255
    int n  = plane >> 7;
    int co = plane & 127;
    __shared__ float ys[4 * 1156];
    for (int idx = threadIdx.x; idx < 4 * 1156; idx += 256) {
        int ci = idx / 1156, rr = idx - ci * 1156;
        int r = rr / 34, c = rr - r * 34;
        int gr = r - 1, gc = c - 1;
        ys[idx] = ((unsigned)gr < 32u && (unsigned)gc < 32u)
                  ? g_ygn[(n * 4 + ci) * 1024 + gr * 32 + gc] : 0.f;
    }
    __syncthreads();

    const float* wgt = pw + co * 36;
    float bias = pb[co];
    int row  = threadIdx.x >> 3;
    int col0 = (threadIdx.x & 7) << 2;
    float a0 = bias, a1 = bias, a2 = bias, a3 = bias;
#pragma unroll
    for (int ci = 0; ci < 4; ci++) {
        float w[9];
#pragma unroll
        for (int k = 0; k < 9; k++) w[k] = __ldg(wgt + ci * 9 + k);
        float s[3][6];
#pragma unroll
        for (int dy = 0; dy < 3; dy++)
#pragma unroll
            for (int dx = 0; dx < 6; dx++)
                s[dy][dx] = ys[ci * 1156 + (row + dy) * 34 + col0 + dx];
#pragma unroll
        for (int dy = 0; dy < 3; dy++) {
            float w0 = w[dy * 3], w1 = w[dy * 3 + 1], w2 = w[dy * 3 + 2];
            a0 += w0 * s[dy][0] + w1 * s[dy][1] + w2 * s[dy][2];
            a1 += w0 * s[dy][1] + w1 * s[dy][2] + w2 * s[dy][3];
            a2 += w0 * s[dy][2] + w1 * s[dy][3] + w2 * s[dy][4];
            a3 += w0 * s[dy][3] + w1 * s[dy][4] + w2 * s[dy][5];
        }
    }
    float* o = out + ((n * 128 + co) * 1024) + row * 32 + col0;
    o[0] = a0; o[1] = a1; o[2] = a2; o[3] = a3;
}

// ---------------- launcher ----------------
extern "C" void kernel_launch(void* const* d_in, const int* in_sizes, int n_in,
                              void* d_out, int out_size)
{
    const float* x    = (const float*)d_in[0];
    const float* a    = (const float*)d_in[1];
    const float* gw1  = (const float*)d_in[2];
    const float* gb1  = (const float*)d_in[3];
    const float* gw2  = (const float*)d_in[4];
    const float* gb2  = (const float*)d_in[5];
    const float* aw1  = (const float*)d_in[6];
    const float* ab1  = (const float*)d_in[7];
    const float* aw2  = (const float*)d_in[8];
    const float* ab2  = (const float*)d_in[9];
    const float* sw1  = (const float*)d_in[10];
    const float* sb1  = (const float*)d_in[11];
    const float* sw2  = (const float*)d_in[12];
    const float* sb2  = (const float*)d_in[13];
    const float* gn_g = (const float*)d_in[14];
    const float* gn_b = (const float*)d_in[15];
    const float* pw   = (const float*)d_in[16];
    const float* pb   = (const float*)d_in[17];
    float* out = (float*)d_out;

    k_conv1<<<256, 256>>>(x, gw1, gb1, aw1, ab1);
    k_conv2<<<96, 256>>>(gw2, gb2, aw2, ab2);
    k_se<<<2, 256>>>(x, sw1, sb1, sw2, sb2);
    k_build<<<32, 256>>>(a);
    k_solve<<<8, 256>>>();
    k_gn<<<2, 256>>>(gn_g, gn_b);
    k_convf<<<256, 256>>>(pw, pb, out);
}